// round 11
// baseline (speedup 1.0000x reference)
#include <cuda_runtime.h>
#include <math.h>

#define NW 10
#define NP 5                  // wire pairs
#define NQ 4                  // quantities per pair: cc, cs, sc, ss
#define NSAMP 4096
#define TM 128                // X rows per CTA
#define TN 64                 // Y cols per CTA

typedef unsigned long long u64;

// out[x, y] = prod_i cos^2((X[x,i] - Y[y,i]) / 2)
// (unitary invariance: shared-params RZ/CNOT circuit cancels in <psi_x|psi_y>;
//  product-state overlap factorizes per qubit. Wire-pair expansion:
//  (ci*cyi + si*syi)(cj*cyj + sj*syj) = cc*CC + cs*CS + sc*SC + ss*SS.)

// global pair-product tables (device-code references ONLY)
__device__ float2 g_Xd[NP * NQ][NSAMP];   // x side, duplicated (v,v) pairs
__device__ float  g_Yt[NP * NQ][NSAMP];   // y side, natural scalars

__device__ __forceinline__ u64 mul2(u64 a, u64 b) {
    u64 r; asm("mul.rn.f32x2 %0, %1, %2;" : "=l"(r) : "l"(a), "l"(b)); return r;
}
__device__ __forceinline__ u64 fma2(u64 a, u64 b, u64 c) {
    u64 r; asm("fma.rn.f32x2 %0, %1, %2, %3;" : "=l"(r) : "l"(a), "l"(b), "l"(c)); return r;
}

// one thread per sample: build pair-product tables for both sides
__global__ void tab_kernel(const float* __restrict__ X, const float* __restrict__ Y) {
    const int s = blockIdx.x * 256 + threadIdx.x;
#pragma unroll
    for (int p = 0; p < NP; ++p) {
        float si, ci, sj, cj;
        __sincosf(0.5f * X[s * NW + 2 * p],     &si, &ci);
        __sincosf(0.5f * X[s * NW + 2 * p + 1], &sj, &cj);
        float q0 = ci * cj, q1 = ci * sj, q2 = si * cj, q3 = si * sj;
        g_Xd[p * NQ + 0][s] = make_float2(q0, q0);
        g_Xd[p * NQ + 1][s] = make_float2(q1, q1);
        g_Xd[p * NQ + 2][s] = make_float2(q2, q2);
        g_Xd[p * NQ + 3][s] = make_float2(q3, q3);
        __sincosf(0.5f * Y[s * NW + 2 * p],     &si, &ci);
        __sincosf(0.5f * Y[s * NW + 2 * p + 1], &sj, &cj);
        g_Yt[p * NQ + 0][s] = ci * cj;
        g_Yt[p * NQ + 1][s] = ci * sj;
        g_Yt[p * NQ + 2][s] = si * cj;
        g_Yt[p * NQ + 3][s] = si * sj;
    }
}

#define XCHUNKS (NP * NQ * TM / 2)        // 1280 float4 chunks (x dup table)
#define YCHUNKS (NP * NQ * TN / 4)        // 320 float4 chunks
#define NCHUNKS (XCHUNKS + YCHUNKS)       // 1600

__global__ void __launch_bounds__(256, 3)
qk_kernel(float* __restrict__ out) {
    // x: duplicated float2 pairs; y: natural floats (read as packed u64 pairs)
    __shared__ __align__(16) float2 sxd[NP * NQ][TM];
    __shared__ __align__(16) float  syp[NP * NQ][TN];

    const int tid = threadIdx.x;
    const int bn = blockIdx.x * TN;     // Y cols
    const int bm = blockIdx.y * TM;     // X rows

    // prologue: pure coalesced copy of precomputed tables
    {
        float4* dx = (float4*)sxd;
        float4* dy = (float4*)syp;
        for (int c = tid; c < NCHUNKS; c += 256) {
            if (c < XCHUNKS) {
                int pq = c >> 6, off = c & 63;     // 64 chunks per (p,q) row
                dx[pq * 64 + off] = ((const float4*)(&g_Xd[pq][bm]))[off];
            } else {
                int c2 = c - XCHUNKS;
                int pq = c2 >> 4, off = c2 & 15;   // 16 chunks per (p,q) row
                dy[pq * 16 + off] = ((const float4*)(&g_Yt[pq][bn]))[off];
            }
        }
    }
    __syncthreads();

    const int tx = tid & 15;            // col group: 4 cols = 2 packs
    const int ty = tid >> 4;            // row group: 8 rows
    const int r0 = ty * 8;
    const int c0 = tx * 4;

    u64 acc[8][2];

#pragma unroll
    for (int p = 0; p < NP; ++p) {
        // y side: 4 quantities x 4 cols (2 packs each), one LDS.128 per quantity
        ulonglong2 ycc = *(const ulonglong2*)&syp[p * NQ + 0][c0];
        ulonglong2 ycs = *(const ulonglong2*)&syp[p * NQ + 1][c0];
        ulonglong2 ysc = *(const ulonglong2*)&syp[p * NQ + 2][c0];
        ulonglong2 yss = *(const ulonglong2*)&syp[p * NQ + 3][c0];
        u64 y0[4] = {ycc.x, ycs.x, ysc.x, yss.x};
        u64 y1[4] = {ycc.y, ycs.y, ysc.y, yss.y};

#pragma unroll
        for (int h = 0; h < 2; ++h) {
            // x side: duplicated packs, LDS.128 = 2 rows per load (broadcast)
            u64 xs[NQ][4];
#pragma unroll
            for (int q = 0; q < NQ; ++q) {
                ulonglong2 lo = *(const ulonglong2*)&sxd[p * NQ + q][r0 + 4 * h];
                ulonglong2 hi = *(const ulonglong2*)&sxd[p * NQ + q][r0 + 4 * h + 2];
                xs[q][0] = lo.x; xs[q][1] = lo.y; xs[q][2] = hi.x; xs[q][3] = hi.y;
            }
#pragma unroll
            for (int r = 0; r < 4; ++r) {
                u64 t0 = mul2(xs[0][r], y0[0]);
                t0 = fma2(xs[1][r], y0[1], t0);
                t0 = fma2(xs[2][r], y0[2], t0);
                t0 = fma2(xs[3][r], y0[3], t0);
                u64 t1 = mul2(xs[0][r], y1[0]);
                t1 = fma2(xs[1][r], y1[1], t1);
                t1 = fma2(xs[2][r], y1[2], t1);
                t1 = fma2(xs[3][r], y1[3], t1);
                const int rr = 4 * h + r;
                if (p == 0) {
                    acc[rr][0] = t0;
                    acc[rr][1] = t1;
                } else {
                    acc[rr][0] = mul2(acc[rr][0], t0);
                    acc[rr][1] = mul2(acc[rr][1], t1);
                }
            }
        }
    }

    // epilogue: square packed, one 16B store per row
#pragma unroll
    for (int r = 0; r < 8; ++r) {
        ulonglong2 v;
        v.x = mul2(acc[r][0], acc[r][0]);
        v.y = mul2(acc[r][1], acc[r][1]);
        *(ulonglong2*)(out + (size_t)(bm + r0 + r) * NSAMP + bn + c0) = v;
    }
}

extern "C" void kernel_launch(void* const* d_in, const int* in_sizes, int n_in,
                              void* d_out, int out_size) {
    const float* X = (const float*)d_in[0];      // (4096, 10)
    const float* Y = (const float*)d_in[1];      // (4096, 10)
    // d_in[2] (params) provably does not affect the output (unitary invariance)
    float* out = (float*)d_out;                  // (4096, 4096)

    tab_kernel<<<NSAMP / 256, 256>>>(X, Y);

    dim3 grid(NSAMP / TN, NSAMP / TM);           // (64, 32)
    qk_kernel<<<grid, 256>>>(out);
}